// round 9
// baseline (speedup 1.0000x reference)
#include <cuda_runtime.h>
#include <cstdint>
#include <math.h>

#define EPS 1e-8f
#define RAD2DEG 57.295779513082320876798154814105f

#define THREADS    128
#define NWARP      4
#define TILE_ROWS  128        // per CTA; 32 rows per warp
#define WROWS      32
#define QCOLS      4          // float4 per row per quarter (16 floats)
#define NBUF       3          // ring depth (>= prefetch distance 2 + 1)
#define WBUF_F     (WROWS * 16)   // floats per warp-buffer (2KB)

// Inputs: data [N,64] f32, lab [N,3] f32, W [64,3] f32, b [3] f32 ; out [N] f32
//
// Persistent CTAs; WARP-AUTONOMOUS pipelines. Each warp owns 32 rows of each
// 128-row tile and runs a private 3-deep cp.async ring (distance 2). Sync is
// cp.async.wait_group + __syncwarp only -- zero block barriers in the main
// loop, so warps free-run their load/compute overlap. XOR swizzle
// (c ^ ((r>>1)&3)) keeps rows at exactly 16 floats with conflict-free
// STS/LDS. Total smem 24KB + W -> 8 CTAs/SM.

__device__ __forceinline__ void cp_async16(unsigned int dst, const void* src) {
    asm volatile("cp.async.cg.shared.global [%0], [%1], 16;\n"
                 :: "r"(dst), "l"(src));
}
__device__ __forceinline__ void cp_commit() {
    asm volatile("cp.async.commit_group;\n");
}
template <int n>
__device__ __forceinline__ void cp_wait() {
    asm volatile("cp.async.wait_group %0;\n" :: "n"(n));
}

__global__ __launch_bounds__(THREADS, 8) void cosine_loss_kernel(
    const float* __restrict__ data,
    const float* __restrict__ lab,
    const float* __restrict__ W,
    const float* __restrict__ b,
    float* __restrict__ out,
    int N, int ntiles)
{
    __shared__ __align__(16) float sbuf[NBUF][NWARP][WBUF_F];  // 24 KB
    __shared__ __align__(16) float sW[3][64];
    __shared__ float sb[3];

    const int t = threadIdx.x;
    const int w = t >> 5;     // warp id 0..3
    const int l = t & 31;     // lane

    // Stage W transposed to [3][64] and b; one barrier, then warps free-run.
    if (t < 192) { int k = t / 3, c = t % 3; sW[c][k] = W[t]; }
    {
        int i = t + 128;
        if (i < 192) { int k = i / 3, c = i % 3; sW[c][k] = W[i]; }
    }
    if (t < 3) sb[t] = b[t];
    __syncthreads();

    const int nslots = (ntiles - blockIdx.x + (int)gridDim.x - 1) / (int)gridDim.x;
    const int nitems = 4 * nslots;
    if (nitems == 0) return;

    // Per-lane staging geometry: instruction j covers rows j*8..j*8+7,
    // lane -> (r = j*8 + (l>>2), c = l&3), contiguous 16B across 4 lanes.
    const int pr = l >> 2;          // row-within-8 for this lane
    const int pc = l & 3;           // float4 col for this lane

    // Stage one (tile, quarter) item into this warp's region of ring buffer.
    auto prefetch = [&](int item) {
        int slot = item >> 2;
        int q    = item & 3;
        int tile = blockIdx.x + slot * gridDim.x;
        int row0 = tile * TILE_ROWS + w * WROWS;
        const float4* gsrc = reinterpret_cast<const float4*>(data);
        unsigned int sdst =
            (unsigned int)__cvta_generic_to_shared(&sbuf[item % NBUF][w][0]);
        #pragma unroll
        for (int j = 0; j < 4; ++j) {
            int r = j * 8 + pr;                 // 0..31
            int cs = pc ^ ((r >> 1) & 3);       // swizzled col slot
            int row = row0 + r;
            if (row < N) {
                const float4* src = &gsrc[(size_t)row * 16 + q * QCOLS + pc];
                cp_async16(sdst + (unsigned int)((r * 16 + cs * 4) * 4), src);
            }
        }
        cp_commit();
    };

    // Prime (distance 2).
    prefetch(0);
    if (nitems > 1) prefetch(1); else cp_commit();

    const float4* __restrict__ w0v = reinterpret_cast<const float4*>(sW[0]);
    const float4* __restrict__ w1v = reinterpret_cast<const float4*>(sW[1]);
    const float4* __restrict__ w2v = reinterpret_cast<const float4*>(sW[2]);

    const int myswz = (l >> 1) & 3;   // this lane's row swizzle (row == lane)

    float acc0 = 0.f, acc1 = 0.f, acc2 = 0.f;
    float l0 = 0.f, l1 = 0.f, l2 = 0.f;
    int cur_row = -1;

    for (int item = 0; item < nitems; ++item) {
        cp_wait<1>();        // own groups done (<= distance-1 outstanding)
        __syncwarp();        // all lanes' waits done -> warp buffer visible

        const int slot = item >> 2;
        const int q    = item & 3;
        const int tile = blockIdx.x + slot * gridDim.x;
        const int row  = tile * TILE_ROWS + w * WROWS + l;
        const bool live = (row < N);

        const float4* __restrict__ dv =
            reinterpret_cast<const float4*>(&sbuf[item % NBUF][w][l * 16]);

        if (q == 0) {
            acc0 = acc1 = acc2 = 0.f;
            cur_row = row;
            if (live) {
                const float* lr = lab + (size_t)row * 3;
                l0 = __ldg(&lr[0]); l1 = __ldg(&lr[1]); l2 = __ldg(&lr[2]);
            }
        }

        #pragma unroll
        for (int k = 0; k < QCOLS; ++k) {
            float4 d  = dv[k ^ myswz];          // undo swizzle
            int kk = q * QCOLS + k;
            float4 w0 = w0v[kk];
            float4 w1 = w1v[kk];
            float4 w2 = w2v[kk];
            acc0 += d.x * w0.x + d.y * w0.y + d.z * w0.z + d.w * w0.w;
            acc1 += d.x * w1.x + d.y * w1.y + d.z * w1.z + d.w * w1.w;
            acc2 += d.x * w2.x + d.y * w2.y + d.z * w2.z + d.w * w2.w;
        }

        if (q == 3 && live) {
            float p0 = acc0 + sb[0];
            float p1 = acc1 + sb[1];
            float p2 = acc2 + sb[2];

            float n = sqrtf(p0 * p0 + p1 * p1 + p2 * p2);
            float inv = 1.0f / fmaxf(n, EPS);
            float pn0 = p0 * inv, pn1 = p1 * inv, pn2 = p2 * inv;

            float dot = pn0 * l0 + pn1 * l1 + pn2 * l2;
            float na = fmaxf(sqrtf(pn0 * pn0 + pn1 * pn1 + pn2 * pn2), EPS);
            float nb = fmaxf(sqrtf(l0 * l0 + l1 * l1 + l2 * l2), EPS);
            float cosv = dot / (na * nb);

            float loss = acosf(cosv) * RAD2DEG;
            if (isnan(loss)) loss = 0.0f;
            out[cur_row] = loss;
        }

        __syncwarp();        // readers of buffer (item%NBUF) retired

        // Ring depth 3 >= distance 2 + 1: buffer (item+2)%NBUF was last read
        // at item-1, ordered by the syncwarp above.
        int nxt = item + 2;
        if (nxt < nitems) prefetch(nxt);
        else              cp_commit();   // uniform group accounting
    }
}

extern "C" void kernel_launch(void* const* d_in, const int* in_sizes, int n_in,
                              void* d_out, int out_size)
{
    const float* data = (const float*)d_in[0];
    const float* lab  = (const float*)d_in[1];
    const float* W    = (const float*)d_in[2];
    const float* b    = (const float*)d_in[3];
    float* out = (float*)d_out;

    int N = in_sizes[0] / 64;
    int ntiles = (N + TILE_ROWS - 1) / TILE_ROWS;
    int blocks = 148 * 8;              // persistent: 8 CTAs per SM
    if (blocks > ntiles) blocks = ntiles;
    cosine_loss_kernel<<<blocks, THREADS>>>(data, lab, W, b, out, N, ntiles);
}

// round 10
// speedup vs baseline: 1.0762x; 1.0762x over previous
#include <cuda_runtime.h>
#include <cstdint>
#include <math.h>

#define EPS 1e-8f
#define RAD2DEG 57.295779513082320876798154814105f

#define THREADS    128
#define TILE_ROWS  128
#define QCOLS      4          // float4 per row per quarter-tile (16 floats)
#define SSTRIDE    16         // floats per row (no pad; XOR swizzle)
#define NBUF       3          // ring depth (>= prefetch distance 2 + 1)

// Inputs: data [N,64] f32, lab [N,3] f32, W [64,3] f32, b [3] f32 ; out [N] f32
//
// Round-7 structure (quarter-tile cp.async ring, one block barrier per item,
// 8 CTAs/SM) + DYNAMIC WORK STEALING: tiles are handed out via a global
// atomic counter so no CTA idles in a static-remainder tail. The next tile
// id is fetched one tile ahead (atomicAdd at q==3, smem broadcast, consumed
// after the q==0 barrier) so the distance-2 prefetch pipeline never stalls.

__device__ unsigned int g_tile_ctr;

__global__ void init_ctr_kernel(unsigned int v) { g_tile_ctr = v; }

__device__ __forceinline__ void cp_async16(unsigned int dst, const void* src) {
    asm volatile("cp.async.cg.shared.global [%0], [%1], 16;\n"
                 :: "r"(dst), "l"(src));
}
__device__ __forceinline__ void cp_commit() {
    asm volatile("cp.async.commit_group;\n");
}
template <int n>
__device__ __forceinline__ void cp_wait() {
    asm volatile("cp.async.wait_group %0;\n" :: "n"(n));
}

__global__ __launch_bounds__(THREADS, 8) void cosine_loss_kernel(
    const float* __restrict__ data,
    const float* __restrict__ lab,
    const float* __restrict__ W,
    const float* __restrict__ b,
    float* __restrict__ out,
    int N, int ntiles)
{
    __shared__ __align__(16) float sbuf[NBUF][TILE_ROWS * SSTRIDE]; // 3 x 8KB
    __shared__ __align__(16) float sW[3][64];
    __shared__ float sb[3];
    __shared__ int s_next;

    const int t = threadIdx.x;

    if (t < 192) { int k = t / 3, c = t % 3; sW[c][k] = W[t]; }
    {
        int i = t + 128;
        if (i < 192) { int k = i / 3, c = i % 3; sW[c][k] = W[i]; }
    }
    if (t < 3) sb[t] = b[t];

    int tile_cur = blockIdx.x;
    if (t == 0) s_next = (int)atomicAdd(&g_tile_ctr, 1u);
    __syncthreads();                       // W/b staged + s_next visible
    int tile_next = s_next;

    // Stage quarter q of `tile` into sbuf[slot].
    auto prefetch = [&](int tile, int q, int slot) {
        if (tile >= ntiles) { cp_commit(); return; }
        int row0 = tile * TILE_ROWS;
        const float4* gsrc = reinterpret_cast<const float4*>(data);
        unsigned int sdst =
            (unsigned int)__cvta_generic_to_shared(&sbuf[slot][0]);
        #pragma unroll
        for (int j = 0; j < QCOLS; ++j) {
            int v = j * THREADS + t;          // 0..511 float4s in quarter-tile
            int r = v >> 2;                   // local row
            int c = v & 3;                    // float4 within quarter-row
            int cs = c ^ ((r >> 1) & 3);      // swizzled column slot
            int row = row0 + r;
            if (row < N) {
                const float4* src = &gsrc[(size_t)row * 16 + q * QCOLS + c];
                cp_async16(sdst + (unsigned int)((r * SSTRIDE + cs * 4) * 4), src);
            }
        }
        cp_commit();
    };

    // Prime pipeline (distance 2): quarters 0,1 of the first tile.
    prefetch(tile_cur, 0, 0);
    prefetch(tile_cur, 1, 1);

    const float4* __restrict__ w0v = reinterpret_cast<const float4*>(sW[0]);
    const float4* __restrict__ w1v = reinterpret_cast<const float4*>(sW[1]);
    const float4* __restrict__ w2v = reinterpret_cast<const float4*>(sW[2]);

    const int myswz = (t >> 1) & 3;

    float acc0 = 0.f, acc1 = 0.f, acc2 = 0.f;
    float l0 = 0.f, l1 = 0.f, l2 = 0.f;
    int item = 0;

    while (tile_cur < ntiles) {
        const int row  = tile_cur * TILE_ROWS + t;
        const bool live = (row < N);

        #pragma unroll
        for (int q = 0; q < 4; ++q, ++item) {
            cp_wait<1>();
            __syncthreads();   // buffer (item%NBUF) staged; prior reads done

            if (q == 0) {
                tile_next = s_next;            // written at q==3 of prev tile
                acc0 = acc1 = acc2 = 0.f;
                if (live) {
                    const float* lr = lab + (size_t)row * 3;
                    l0 = __ldg(&lr[0]); l1 = __ldg(&lr[1]); l2 = __ldg(&lr[2]);
                }
            }

            const float4* __restrict__ dv =
                reinterpret_cast<const float4*>(&sbuf[item % NBUF][t * SSTRIDE]);

            #pragma unroll
            for (int k = 0; k < QCOLS; ++k) {
                float4 d  = dv[k ^ myswz];
                int kk = q * QCOLS + k;
                float4 w0 = w0v[kk];
                float4 w1 = w1v[kk];
                float4 w2 = w2v[kk];
                acc0 += d.x * w0.x + d.y * w0.y + d.z * w0.z + d.w * w0.w;
                acc1 += d.x * w1.x + d.y * w1.y + d.z * w1.z + d.w * w1.w;
                acc2 += d.x * w2.x + d.y * w2.y + d.z * w2.z + d.w * w2.w;
            }

            if (q == 3) {
                if (live) {
                    float p0 = acc0 + sb[0];
                    float p1 = acc1 + sb[1];
                    float p2 = acc2 + sb[2];

                    float n = sqrtf(p0 * p0 + p1 * p1 + p2 * p2);
                    float inv = 1.0f / fmaxf(n, EPS);
                    float pn0 = p0 * inv, pn1 = p1 * inv, pn2 = p2 * inv;

                    float dot = pn0 * l0 + pn1 * l1 + pn2 * l2;
                    float na = fmaxf(sqrtf(pn0*pn0 + pn1*pn1 + pn2*pn2), EPS);
                    float nb = fmaxf(sqrtf(l0*l0 + l1*l1 + l2*l2), EPS);
                    float cosv = dot / (na * nb);

                    float loss = acosf(cosv) * RAD2DEG;
                    if (isnan(loss)) loss = 0.0f;
                    out[row] = loss;
                }
                // Fetch the tile after tile_next (consumed at next q==0).
                if (t == 0 && tile_next < ntiles)
                    s_next = (int)atomicAdd(&g_tile_ctr, 1u);
            }

            // Prefetch item+2: quarter (q+2)&3 of tile_cur (q<2) or tile_next.
            int pq    = (q + 2) & 3;
            int ptile = (q < 2) ? tile_cur : tile_next;
            prefetch(ptile, pq, (item + 2) % NBUF);
        }

        tile_cur = tile_next;
    }
}

extern "C" void kernel_launch(void* const* d_in, const int* in_sizes, int n_in,
                              void* d_out, int out_size)
{
    const float* data = (const float*)d_in[0];
    const float* lab  = (const float*)d_in[1];
    const float* W    = (const float*)d_in[2];
    const float* b    = (const float*)d_in[3];
    float* out = (float*)d_out;

    int N = in_sizes[0] / 64;
    int ntiles = (N + TILE_ROWS - 1) / TILE_ROWS;
    int blocks = 148 * 8;
    if (blocks > ntiles) blocks = ntiles;

    init_ctr_kernel<<<1, 1>>>((unsigned int)blocks);
    cosine_loss_kernel<<<blocks, THREADS>>>(data, lab, W, b, out, N, ntiles);
}